// round 7
// baseline (speedup 1.0000x reference)
#include <cuda_runtime.h>
#include <cuda_bf16.h>

// B=8, H=8, L=2048, D=64, BH=64
#define LSEQ 2048
#define DH   64

// deterministic per-row partial sums: [64*2048 rows][16 col-tiles]
__device__ float g_partial[64 * 2048 * 16];

// ---------- helpers ----------
__device__ __forceinline__ unsigned f2tf(float f) {
    unsigned u;
    asm("cvt.rna.tf32.f32 %0, %1;" : "=r"(u) : "f"(f));
    return u;
}

__device__ __forceinline__ void mma8(float* c, const unsigned* a, unsigned b0, unsigned b1) {
    asm volatile(
        "mma.sync.aligned.m16n8k8.row.col.f32.tf32.tf32.f32 "
        "{%0,%1,%2,%3}, {%4,%5,%6,%7}, {%8,%9}, {%0,%1,%2,%3};"
        : "+f"(c[0]), "+f"(c[1]), "+f"(c[2]), "+f"(c[3])
        : "r"(a[0]), "r"(a[1]), "r"(a[2]), "r"(a[3]), "r"(b0), "r"(b1));
}

// exp(x) via FMA-pipe polynomial (no MUFU). |x| is tiny here (<~1).
__device__ __forceinline__ float fexp(float x) {
    x = fmaxf(fminf(x, 80.0f), -80.0f);
    const float L2E = 1.4426950408889634f;
    float t = fmaf(x, L2E, 12582912.0f);
    float n = t - 12582912.0f;
    float f = fmaf(x, L2E, -n);
    float p = 1.33335581e-3f;
    p = fmaf(p, f, 9.61812910e-3f);
    p = fmaf(p, f, 5.55041086e-2f);
    p = fmaf(p, f, 2.40226507e-1f);
    p = fmaf(p, f, 6.93147181e-1f);
    p = fmaf(p, f, 1.0f);
    unsigned bits = (unsigned)(((int)n + 127) << 23);
    return p * __uint_as_float(bits);
}

// =====================================================================
// K1: e = exp((Q K^T)/64) -> att buffer (unnormalized), + partial row sums.
// CTA: 128x128 tile. 256 threads, warp tile 64x32.
// =====================================================================
#define ASTR 68    // staging stride (mod 32 == 4)
#define ESTR 136   // epilogue e-tile stride (mod 32 == 8 -> conflict-free STS)
// smem: staging 2*128*68 = 17408 floats == epilogue overlay 128*136 = 17408;
// + sRowW [4][128] = 512 floats  (R5 bug: was 256 -> OOB smem write)
#define K1_SMEM_FLOATS (17408 + 512)
#define K1_SMEM_BYTES  (K1_SMEM_FLOATS * 4)

__global__ __launch_bounds__(256)
void qk2_kernel(const float* __restrict__ Q, const float* __restrict__ K,
                float* __restrict__ att) {
    extern __shared__ float sm[];
    float* sQ = sm;                 // [128][ASTR]
    float* sK = sm + 128 * ASTR;    // [128][ASTR]
    float* sE = sm;                 // overlay: [128][ESTR]
    float* sRowW = sm + 17408;      // [4][128]
    float4* sQ4 = (float4*)sQ;
    float4* sK4 = (float4*)sK;
    float4* sE4 = (float4*)sE;

    const int nt = blockIdx.x, mt = blockIdx.y, bh = blockIdx.z;
    const int tid = threadIdx.x;
    const int warp = tid >> 5, lane = tid & 31;
    const int g = lane >> 2, tg = lane & 3;
    const int wm = warp >> 2;   // 0..1
    const int wn = warp & 3;    // 0..3

    const float4* Qg = (const float4*)(Q + ((size_t)bh * LSEQ + (size_t)mt * 128) * DH);
    const float4* Kg = (const float4*)(K + ((size_t)bh * LSEQ + (size_t)nt * 128) * DH);

    const float inv_d = 1.0f / 64.0f;
    #pragma unroll
    for (int i = 0; i < 8; i++) {
        int idx = tid + i * 256;
        int row = idx >> 4, c4 = idx & 15;
        float4 q = Qg[row * 16 + c4];
        q.x = __uint_as_float(f2tf(q.x * inv_d));
        q.y = __uint_as_float(f2tf(q.y * inv_d));
        q.z = __uint_as_float(f2tf(q.z * inv_d));
        q.w = __uint_as_float(f2tf(q.w * inv_d));
        sQ4[row * (ASTR / 4) + c4] = q;
        float4 k = Kg[row * 16 + c4];
        k.x = __uint_as_float(f2tf(k.x));
        k.y = __uint_as_float(f2tf(k.y));
        k.z = __uint_as_float(f2tf(k.z));
        k.w = __uint_as_float(f2tf(k.w));
        sK4[row * (ASTR / 4) + c4] = k;
    }
    __syncthreads();

    float acc[4][4][4];
    #pragma unroll
    for (int mi = 0; mi < 4; mi++)
        #pragma unroll
        for (int ni = 0; ni < 4; ni++)
            #pragma unroll
            for (int j = 0; j < 4; j++) acc[mi][ni][j] = 0.f;

    #pragma unroll
    for (int ks = 0; ks < 8; ks++) {
        unsigned a[4][4], b[4][2];
        #pragma unroll
        for (int mi = 0; mi < 4; mi++) {
            int row = wm * 64 + mi * 16;
            a[mi][0] = __float_as_uint(sQ[(row + g) * ASTR + ks * 8 + tg]);
            a[mi][1] = __float_as_uint(sQ[(row + 8 + g) * ASTR + ks * 8 + tg]);
            a[mi][2] = __float_as_uint(sQ[(row + g) * ASTR + ks * 8 + tg + 4]);
            a[mi][3] = __float_as_uint(sQ[(row + 8 + g) * ASTR + ks * 8 + tg + 4]);
        }
        #pragma unroll
        for (int ni = 0; ni < 4; ni++) {
            int col = wn * 32 + ni * 8;
            b[ni][0] = __float_as_uint(sK[(col + g) * ASTR + ks * 8 + tg]);
            b[ni][1] = __float_as_uint(sK[(col + g) * ASTR + ks * 8 + tg + 4]);
        }
        #pragma unroll
        for (int mi = 0; mi < 4; mi++)
            #pragma unroll
            for (int ni = 0; ni < 4; ni++)
                mma8(acc[mi][ni], a[mi], b[ni][0], b[ni][1]);
    }
    __syncthreads();   // staging dead; sE overlay begins

    // ---- epilogue: e = exp(s), per-row partial sums, smem-staged store ----
    float rs0[4] = {0.f, 0.f, 0.f, 0.f};
    float rs1[4] = {0.f, 0.f, 0.f, 0.f};
    #pragma unroll
    for (int mi = 0; mi < 4; mi++) {
        int row = wm * 64 + mi * 16 + g;
        #pragma unroll
        for (int ni = 0; ni < 4; ni++) {
            int col = wn * 32 + ni * 8 + 2 * tg;
            float e0 = fexp(acc[mi][ni][0]);
            float e1 = fexp(acc[mi][ni][1]);
            float e2 = fexp(acc[mi][ni][2]);
            float e3 = fexp(acc[mi][ni][3]);
            rs0[mi] += e0 + e1;
            rs1[mi] += e2 + e3;
            *(float2*)&sE[row * ESTR + col]       = make_float2(e0, e1);
            *(float2*)&sE[(row + 8) * ESTR + col] = make_float2(e2, e3);
        }
    }
    #pragma unroll
    for (int o = 1; o <= 2; o <<= 1) {
        #pragma unroll
        for (int mi = 0; mi < 4; mi++) {
            rs0[mi] += __shfl_xor_sync(0xffffffffu, rs0[mi], o);
            rs1[mi] += __shfl_xor_sync(0xffffffffu, rs1[mi], o);
        }
    }
    if (tg == 0) {
        #pragma unroll
        for (int mi = 0; mi < 4; mi++) {
            sRowW[wn * 128 + wm * 64 + mi * 16 + g]     = rs0[mi];
            sRowW[wn * 128 + wm * 64 + mi * 16 + 8 + g] = rs1[mi];
        }
    }
    __syncthreads();

    // coalesced store of e tile (512B per row)
    float4* attT = (float4*)(att + ((size_t)bh * LSEQ + (size_t)mt * 128) * LSEQ
                                 + (size_t)nt * 128);
    #pragma unroll
    for (int i = 0; i < 16; i++) {
        int idx = tid + i * 256;          // 0..4095
        int row = idx >> 5, c4 = idx & 31;
        attT[(size_t)row * 512 + c4] = sE4[row * (ESTR / 4) + c4];
    }
    if (tid < 128) {
        // wn partials combined in fixed order -> deterministic
        float s = (sRowW[tid] + sRowW[128 + tid]) +
                  (sRowW[256 + tid] + sRowW[384 + tid]);
        g_partial[((size_t)bh * 2048 + (size_t)mt * 128 + tid) * 16 + nt] = s;
    }
}

// =====================================================================
// K2: normalize att in place + res = att @ V.
// CTA: 64 rows x 64 dh. 256 threads, warp tile 16x32.
// =====================================================================
#define PSTR 68
#define VSTR 72

__global__ __launch_bounds__(256)
void av2_kernel(float* att, const float* __restrict__ V,
                float* __restrict__ res) {
    __shared__ float sP[64 * PSTR];
    __shared__ float sV[64 * VSTR];
    __shared__ float sInv[64];
    float4* sP4 = (float4*)sP;
    float4* sV4 = (float4*)sV;

    const int mt = blockIdx.x, bh = blockIdx.y;
    const int tid = threadIdx.x;
    const int warp = tid >> 5, lane = tid & 31;
    const int g = lane >> 2, tg = lane & 3;
    const int wm = warp >> 1;   // 0..3
    const int wn = warp & 1;    // 0..1

    if (tid < 64) {
        const float* p = &g_partial[((size_t)bh * 2048 + (size_t)mt * 64 + tid) * 16];
        float s = 0.f;
        #pragma unroll
        for (int j = 0; j < 16; j++) s += p[j];
        sInv[tid] = 1.0f / s;
    }
    __syncthreads();

    float4* Pg = (float4*)(att + ((size_t)bh * LSEQ + (size_t)mt * 64) * LSEQ);
    const float4* Vg = (const float4*)(V + (size_t)bh * LSEQ * DH);

    float acc[4][4];
    #pragma unroll
    for (int ni = 0; ni < 4; ni++)
        #pragma unroll
        for (int j = 0; j < 4; j++) acc[ni][j] = 0.f;

    for (int kt = 0; kt < 32; kt++) {
        #pragma unroll
        for (int i = 0; i < 4; i++) {
            int idx = tid + i * 256;
            int row = idx >> 4, c4 = idx & 15;
            float4 a = Pg[(size_t)row * 512 + kt * 16 + c4];
            float inv = sInv[row];
            a.x *= inv; a.y *= inv; a.z *= inv; a.w *= inv;
            Pg[(size_t)row * 512 + kt * 16 + c4] = a;   // normalized att, in place
            a.x = __uint_as_float(f2tf(a.x));
            a.y = __uint_as_float(f2tf(a.y));
            a.z = __uint_as_float(f2tf(a.z));
            a.w = __uint_as_float(f2tf(a.w));
            sP4[row * (PSTR / 4) + c4] = a;
            float4 b = Vg[(kt * 64 + row) * 16 + c4];
            b.x = __uint_as_float(f2tf(b.x));
            b.y = __uint_as_float(f2tf(b.y));
            b.z = __uint_as_float(f2tf(b.z));
            b.w = __uint_as_float(f2tf(b.w));
            sV4[row * (VSTR / 4) + c4] = b;
        }
        __syncthreads();

        #pragma unroll
        for (int ks = 0; ks < 8; ks++) {
            unsigned a[4], b[4][2];
            int row0 = wm * 16;
            a[0] = __float_as_uint(sP[(row0 + g) * PSTR + ks * 8 + tg]);
            a[1] = __float_as_uint(sP[(row0 + 8 + g) * PSTR + ks * 8 + tg]);
            a[2] = __float_as_uint(sP[(row0 + g) * PSTR + ks * 8 + tg + 4]);
            a[3] = __float_as_uint(sP[(row0 + 8 + g) * PSTR + ks * 8 + tg + 4]);
            #pragma unroll
            for (int ni = 0; ni < 4; ni++) {
                int col = wn * 32 + ni * 8;
                b[ni][0] = __float_as_uint(sV[(ks * 8 + tg) * VSTR + col + g]);
                b[ni][1] = __float_as_uint(sV[(ks * 8 + tg + 4) * VSTR + col + g]);
            }
            #pragma unroll
            for (int ni = 0; ni < 4; ni++)
                mma8(acc[ni], a, b[ni][0], b[ni][1]);
        }
        __syncthreads();
    }

    float* resR = res + ((size_t)bh * LSEQ + (size_t)mt * 64) * DH;
    #pragma unroll
    for (int ni = 0; ni < 4; ni++) {
        int row = wm * 16 + g;
        int col = wn * 32 + ni * 8 + 2 * tg;
        *(float2*)&resR[(size_t)row * DH + col] = make_float2(acc[ni][0], acc[ni][1]);
        *(float2*)&resR[(size_t)(row + 8) * DH + col] = make_float2(acc[ni][2], acc[ni][3]);
    }
}

// =====================================================================
extern "C" void kernel_launch(void* const* d_in, const int* in_sizes, int n_in,
                              void* d_out, int out_size) {
    const float* Q = (const float*)d_in[0];
    const float* K = (const float*)d_in[1];
    const float* V = (const float*)d_in[2];

    float* out = (float*)d_out;
    float* res = out;
    float* att = out + (size_t)8 * 8 * 2048 * 64;

    cudaFuncSetAttribute(qk2_kernel,
        cudaFuncAttributeMaxDynamicSharedMemorySize, K1_SMEM_BYTES);

    dim3 gA(16, 16, 64);
    qk2_kernel<<<gA, 256, K1_SMEM_BYTES>>>(Q, K, att);

    dim3 gC(32, 64);
    av2_kernel<<<gC, 256>>>(att, V, res);
}

// round 8
// speedup vs baseline: 1.1981x; 1.1981x over previous
#include <cuda_runtime.h>
#include <cuda_bf16.h>

// B=8, H=8, L=2048, D=64, BH=64
#define LSEQ 2048
#define DH   64

// deterministic per-row partial sums: [64*2048 rows][16 col-tiles]
__device__ float g_partial[64 * 2048 * 16];

// ---------- helpers ----------
__device__ __forceinline__ unsigned f2tf(float f) {
    unsigned u;
    asm("cvt.rna.tf32.f32 %0, %1;" : "=r"(u) : "f"(f));
    return u;
}

__device__ __forceinline__ void mma8(float* c, const unsigned* a, unsigned b0, unsigned b1) {
    asm volatile(
        "mma.sync.aligned.m16n8k8.row.col.f32.tf32.tf32.f32 "
        "{%0,%1,%2,%3}, {%4,%5,%6,%7}, {%8,%9}, {%0,%1,%2,%3};"
        : "+f"(c[0]), "+f"(c[1]), "+f"(c[2]), "+f"(c[3])
        : "r"(a[0]), "r"(a[1]), "r"(a[2]), "r"(a[3]), "r"(b0), "r"(b1));
}

__device__ __forceinline__ void cpa16(unsigned s, const void* g) {
    asm volatile("cp.async.cg.shared.global [%0], [%1], 16;" :: "r"(s), "l"(g));
}

// exp(x) via FMA-pipe polynomial (no MUFU). |x| tiny here.
__device__ __forceinline__ float fexp(float x) {
    x = fmaxf(fminf(x, 80.0f), -80.0f);
    const float L2E = 1.4426950408889634f;
    float t = fmaf(x, L2E, 12582912.0f);
    float n = t - 12582912.0f;
    float f = fmaf(x, L2E, -n);
    float p = 1.33335581e-3f;
    p = fmaf(p, f, 9.61812910e-3f);
    p = fmaf(p, f, 5.55041086e-2f);
    p = fmaf(p, f, 2.40226507e-1f);
    p = fmaf(p, f, 6.93147181e-1f);
    p = fmaf(p, f, 1.0f);
    unsigned bits = (unsigned)(((int)n + 127) << 23);
    return p * __uint_as_float(bits);
}

// =====================================================================
// K1: e = exp((Q K^T)/64) -> att (unnormalized), + partial row sums.
// (unchanged from R6 passing version)
// =====================================================================
#define ASTR 68
#define ESTR 136
#define K1_SMEM_FLOATS (17408 + 512)
#define K1_SMEM_BYTES  (K1_SMEM_FLOATS * 4)

__global__ __launch_bounds__(256)
void qk2_kernel(const float* __restrict__ Q, const float* __restrict__ K,
                float* __restrict__ att) {
    extern __shared__ float sm[];
    float* sQ = sm;
    float* sK = sm + 128 * ASTR;
    float* sE = sm;
    float* sRowW = sm + 17408;
    float4* sQ4 = (float4*)sQ;
    float4* sK4 = (float4*)sK;
    float4* sE4 = (float4*)sE;

    const int nt = blockIdx.x, mt = blockIdx.y, bh = blockIdx.z;
    const int tid = threadIdx.x;
    const int warp = tid >> 5, lane = tid & 31;
    const int g = lane >> 2, tg = lane & 3;
    const int wm = warp >> 2;
    const int wn = warp & 3;

    const float4* Qg = (const float4*)(Q + ((size_t)bh * LSEQ + (size_t)mt * 128) * DH);
    const float4* Kg = (const float4*)(K + ((size_t)bh * LSEQ + (size_t)nt * 128) * DH);

    const float inv_d = 1.0f / 64.0f;
    #pragma unroll
    for (int i = 0; i < 8; i++) {
        int idx = tid + i * 256;
        int row = idx >> 4, c4 = idx & 15;
        float4 q = Qg[row * 16 + c4];
        q.x = __uint_as_float(f2tf(q.x * inv_d));
        q.y = __uint_as_float(f2tf(q.y * inv_d));
        q.z = __uint_as_float(f2tf(q.z * inv_d));
        q.w = __uint_as_float(f2tf(q.w * inv_d));
        sQ4[row * (ASTR / 4) + c4] = q;
        float4 k = Kg[row * 16 + c4];
        k.x = __uint_as_float(f2tf(k.x));
        k.y = __uint_as_float(f2tf(k.y));
        k.z = __uint_as_float(f2tf(k.z));
        k.w = __uint_as_float(f2tf(k.w));
        sK4[row * (ASTR / 4) + c4] = k;
    }
    __syncthreads();

    float acc[4][4][4];
    #pragma unroll
    for (int mi = 0; mi < 4; mi++)
        #pragma unroll
        for (int ni = 0; ni < 4; ni++)
            #pragma unroll
            for (int j = 0; j < 4; j++) acc[mi][ni][j] = 0.f;

    #pragma unroll
    for (int ks = 0; ks < 8; ks++) {
        unsigned a[4][4], b[4][2];
        #pragma unroll
        for (int mi = 0; mi < 4; mi++) {
            int row = wm * 64 + mi * 16;
            a[mi][0] = __float_as_uint(sQ[(row + g) * ASTR + ks * 8 + tg]);
            a[mi][1] = __float_as_uint(sQ[(row + 8 + g) * ASTR + ks * 8 + tg]);
            a[mi][2] = __float_as_uint(sQ[(row + g) * ASTR + ks * 8 + tg + 4]);
            a[mi][3] = __float_as_uint(sQ[(row + 8 + g) * ASTR + ks * 8 + tg + 4]);
        }
        #pragma unroll
        for (int ni = 0; ni < 4; ni++) {
            int col = wn * 32 + ni * 8;
            b[ni][0] = __float_as_uint(sK[(col + g) * ASTR + ks * 8 + tg]);
            b[ni][1] = __float_as_uint(sK[(col + g) * ASTR + ks * 8 + tg + 4]);
        }
        #pragma unroll
        for (int mi = 0; mi < 4; mi++)
            #pragma unroll
            for (int ni = 0; ni < 4; ni++)
                mma8(acc[mi][ni], a[mi], b[ni][0], b[ni][1]);
    }
    __syncthreads();

    float rs0[4] = {0.f, 0.f, 0.f, 0.f};
    float rs1[4] = {0.f, 0.f, 0.f, 0.f};
    #pragma unroll
    for (int mi = 0; mi < 4; mi++) {
        int row = wm * 64 + mi * 16 + g;
        #pragma unroll
        for (int ni = 0; ni < 4; ni++) {
            int col = wn * 32 + ni * 8 + 2 * tg;
            float e0 = fexp(acc[mi][ni][0]);
            float e1 = fexp(acc[mi][ni][1]);
            float e2 = fexp(acc[mi][ni][2]);
            float e3 = fexp(acc[mi][ni][3]);
            rs0[mi] += e0 + e1;
            rs1[mi] += e2 + e3;
            *(float2*)&sE[row * ESTR + col]       = make_float2(e0, e1);
            *(float2*)&sE[(row + 8) * ESTR + col] = make_float2(e2, e3);
        }
    }
    #pragma unroll
    for (int o = 1; o <= 2; o <<= 1) {
        #pragma unroll
        for (int mi = 0; mi < 4; mi++) {
            rs0[mi] += __shfl_xor_sync(0xffffffffu, rs0[mi], o);
            rs1[mi] += __shfl_xor_sync(0xffffffffu, rs1[mi], o);
        }
    }
    if (tg == 0) {
        #pragma unroll
        for (int mi = 0; mi < 4; mi++) {
            sRowW[wn * 128 + wm * 64 + mi * 16 + g]     = rs0[mi];
            sRowW[wn * 128 + wm * 64 + mi * 16 + 8 + g] = rs1[mi];
        }
    }
    __syncthreads();

    float4* attT = (float4*)(att + ((size_t)bh * LSEQ + (size_t)mt * 128) * LSEQ
                                 + (size_t)nt * 128);
    #pragma unroll
    for (int i = 0; i < 16; i++) {
        int idx = tid + i * 256;
        int row = idx >> 5, c4 = idx & 31;
        attT[(size_t)row * 512 + c4] = sE4[row * (ESTR / 4) + c4];
    }
    if (tid < 128) {
        float s = (sRowW[tid] + sRowW[128 + tid]) +
                  (sRowW[256 + tid] + sRowW[384 + tid]);
        g_partial[((size_t)bh * 2048 + (size_t)mt * 128 + tid) * 16 + nt] = s;
    }
}

// =====================================================================
// K2 (av3): double-buffered cp.async pipeline.
// normalize att in place + res = att @ V. No register staging, no cvt
// (HMMA truncates f32->tf32; error well under threshold).
// =====================================================================
#define PSTR 68
#define VSTR 72
// floats: sE 2*64*68=8704, sV 2*64*72=9216, sInv 64
#define AV_SMEM_FLOATS (8704 + 9216 + 64)
#define AV_SMEM_BYTES  (AV_SMEM_FLOATS * 4)

__global__ __launch_bounds__(256)
void av3_kernel(float* att, const float* __restrict__ V,
                float* __restrict__ res) {
    extern __shared__ float sm[];
    float* sE   = sm;                 // [2][64*PSTR]
    float* sV   = sm + 8704;          // [2][64*VSTR]
    float* sInv = sm + 8704 + 9216;   // [64]
    const unsigned sbase = (unsigned)__cvta_generic_to_shared(sm);

    const int mt = blockIdx.x, bh = blockIdx.y;
    const int tid = threadIdx.x;
    const int warp = tid >> 5, lane = tid & 31;
    const int g = lane >> 2, tg = lane & 3;
    const int wm = warp >> 1;   // 0..3
    const int wn = warp & 1;    // 0..1

    if (tid < 64) {
        const float* p = &g_partial[((size_t)bh * 2048 + (size_t)mt * 64 + tid) * 16];
        float s = 0.f;
        #pragma unroll
        for (int j = 0; j < 16; j++) s += p[j];
        sInv[tid] = 1.0f / s;
    }

    float4* Pg = (float4*)(att + ((size_t)bh * LSEQ + (size_t)mt * 64) * LSEQ);
    const float4* Vg = (const float4*)(V + (size_t)bh * LSEQ * DH);

    // per-thread staging coords
    const int srow = tid >> 4;          // base row advanced by 16 per i
    const int sc4  = tid & 15;

    // prefetch helper offsets (bytes)
    const unsigned eOff[2] = { 0u, 64u * PSTR * 4u };
    const unsigned vOff[2] = { 8704u * 4u, (8704u + 64u * VSTR) * 4u };

    // ---- prologue: prefetch kt=0 into buffer 0 ----
    {
        #pragma unroll
        for (int i = 0; i < 4; i++) {
            int row = srow + i * 16;
            cpa16(sbase + eOff[0] + (row * PSTR + sc4 * 4) * 4,
                  &Pg[(size_t)row * 512 + sc4]);
            cpa16(sbase + vOff[0] + (row * VSTR + sc4 * 4) * 4,
                  &Vg[row * 16 + sc4]);
        }
        asm volatile("cp.async.commit_group;");
    }

    float acc[4][4];
    #pragma unroll
    for (int ni = 0; ni < 4; ni++)
        #pragma unroll
        for (int j = 0; j < 4; j++) acc[ni][j] = 0.f;

    // row inverses for this warp's fragment rows (fixed across kt)
    __syncthreads();                       // sInv ready (also covers prologue ordering)
    const float invA = sInv[wm * 16 + g];
    const float invB = sInv[wm * 16 + 8 + g];

    for (int kt = 0; kt < 32; kt++) {
        const int cur = kt & 1, nxt = cur ^ 1;
        if (kt + 1 < 32) {
            #pragma unroll
            for (int i = 0; i < 4; i++) {
                int row = srow + i * 16;
                cpa16(sbase + eOff[nxt] + (row * PSTR + sc4 * 4) * 4,
                      &Pg[(size_t)row * 512 + (kt + 1) * 16 + sc4]);
                cpa16(sbase + vOff[nxt] + (row * VSTR + sc4 * 4) * 4,
                      &Vg[((kt + 1) * 64 + row) * 16 + sc4]);
            }
            asm volatile("cp.async.commit_group;");
            asm volatile("cp.async.wait_group 1;");
        } else {
            asm volatile("cp.async.wait_group 0;");
        }
        __syncthreads();

        float* sEc = sE + cur * (64 * PSTR);
        float* sVc = sV + cur * (64 * VSTR);

        // normalized att write (coalesced, in place)
        #pragma unroll
        for (int i = 0; i < 4; i++) {
            int row = srow + i * 16;
            float4 v = *(float4*)&sEc[row * PSTR + sc4 * 4];
            float inv = sInv[row];
            v.x *= inv; v.y *= inv; v.z *= inv; v.w *= inv;
            Pg[(size_t)row * 512 + kt * 16 + sc4] = v;
        }

        // mma (A = e*inv, truncated to tf32 by HW; B = raw V)
        #pragma unroll
        for (int ks = 0; ks < 8; ks++) {
            unsigned a[4], b[4][2];
            int row0 = wm * 16;
            a[0] = __float_as_uint(sEc[(row0 + g) * PSTR + ks * 8 + tg] * invA);
            a[1] = __float_as_uint(sEc[(row0 + 8 + g) * PSTR + ks * 8 + tg] * invB);
            a[2] = __float_as_uint(sEc[(row0 + g) * PSTR + ks * 8 + tg + 4] * invA);
            a[3] = __float_as_uint(sEc[(row0 + 8 + g) * PSTR + ks * 8 + tg + 4] * invB);
            #pragma unroll
            for (int ni = 0; ni < 4; ni++) {
                int col = wn * 32 + ni * 8;
                b[ni][0] = __float_as_uint(sVc[(ks * 8 + tg) * VSTR + col + g]);
                b[ni][1] = __float_as_uint(sVc[(ks * 8 + tg + 4) * VSTR + col + g]);
            }
            #pragma unroll
            for (int ni = 0; ni < 4; ni++)
                mma8(acc[ni], a, b[ni][0], b[ni][1]);
        }
        __syncthreads();   // protect buffer reuse by next prefetch
    }

    float* resR = res + ((size_t)bh * LSEQ + (size_t)mt * 64) * DH;
    #pragma unroll
    for (int ni = 0; ni < 4; ni++) {
        int row = wm * 16 + g;
        int col = wn * 32 + ni * 8 + 2 * tg;
        *(float2*)&resR[(size_t)row * DH + col] = make_float2(acc[ni][0], acc[ni][1]);
        *(float2*)&resR[(size_t)(row + 8) * DH + col] = make_float2(acc[ni][2], acc[ni][3]);
    }
}

// =====================================================================
extern "C" void kernel_launch(void* const* d_in, const int* in_sizes, int n_in,
                              void* d_out, int out_size) {
    const float* Q = (const float*)d_in[0];
    const float* K = (const float*)d_in[1];
    const float* V = (const float*)d_in[2];

    float* out = (float*)d_out;
    float* res = out;
    float* att = out + (size_t)8 * 8 * 2048 * 64;

    cudaFuncSetAttribute(qk2_kernel,
        cudaFuncAttributeMaxDynamicSharedMemorySize, K1_SMEM_BYTES);
    cudaFuncSetAttribute(av3_kernel,
        cudaFuncAttributeMaxDynamicSharedMemorySize, AV_SMEM_BYTES);

    dim3 gA(16, 16, 64);
    qk2_kernel<<<gA, 256, K1_SMEM_BYTES>>>(Q, K, att);

    dim3 gC(32, 64);
    av3_kernel<<<gC, 256, AV_SMEM_BYTES>>>(att, V, res);
}

// round 12
// speedup vs baseline: 1.6246x; 1.3560x over previous
#include <cuda_runtime.h>
#include <cuda_fp16.h>

// B=8, H=8, L=2048, D=64, BH=64
#define LSEQ 2048
#define DH   64

// static device scratch (module-load allocation; allowed)
__device__ __align__(16) __half g_e[(size_t)64 * 2048 * 2048];   // unnormalized exp, fp16
__device__ __align__(16) __half g_qh[(size_t)64 * 2048 * 64];    // Q/64 fp16
__device__ __align__(16) __half g_kh[(size_t)64 * 2048 * 64];    // K fp16
__device__ __align__(16) __half g_vt[(size_t)64 * 64 * 2048];    // V^T fp16 [bh][d][kv]
__device__ float g_partial[64 * 2048 * 16];                      // row-sum partials

// ---------- helpers ----------
__device__ __forceinline__ void mma16(float* c, const unsigned* a,
                                      unsigned b0, unsigned b1) {
    asm volatile(
        "mma.sync.aligned.m16n8k16.row.col.f32.f16.f16.f32 "
        "{%0,%1,%2,%3}, {%4,%5,%6,%7}, {%8,%9}, {%0,%1,%2,%3};"
        : "+f"(c[0]), "+f"(c[1]), "+f"(c[2]), "+f"(c[3])
        : "r"(a[0]), "r"(a[1]), "r"(a[2]), "r"(a[3]), "r"(b0), "r"(b1));
}

__device__ __forceinline__ void cpa16(unsigned s, const void* g) {
    asm volatile("cp.async.cg.shared.global [%0], [%1], 16;" :: "r"(s), "l"(g));
}

// exp(x) via FMA-pipe polynomial (no MUFU).
__device__ __forceinline__ float fexp(float x) {
    x = fmaxf(fminf(x, 80.0f), -80.0f);
    const float L2E = 1.4426950408889634f;
    float t = fmaf(x, L2E, 12582912.0f);
    float n = t - 12582912.0f;
    float f = fmaf(x, L2E, -n);
    float p = 1.33335581e-3f;
    p = fmaf(p, f, 9.61812910e-3f);
    p = fmaf(p, f, 5.55041086e-2f);
    p = fmaf(p, f, 2.40226507e-1f);
    p = fmaf(p, f, 6.93147181e-1f);
    p = fmaf(p, f, 1.0f);
    unsigned bits = (unsigned)(((int)n + 127) << 23);
    return p * __uint_as_float(bits);
}

__device__ __forceinline__ unsigned packh2(float a, float b) {
    __half2 h = __floats2half2_rn(a, b);
    return *(unsigned*)&h;
}

// =====================================================================
// P0: convert Q (scaled by 1/64) and K to fp16.
// =====================================================================
__global__ __launch_bounds__(256)
void prep_qk_kernel(const float* __restrict__ Q, const float* __restrict__ K) {
    size_t i = (size_t)blockIdx.x * 256 + threadIdx.x;   // float4 index
    const float4 q = ((const float4*)Q)[i];
    const float4 k = ((const float4*)K)[i];
    const float s = 1.0f / 64.0f;
    uint2 qo, ko;
    qo.x = packh2(q.x * s, q.y * s);
    qo.y = packh2(q.z * s, q.w * s);
    ko.x = packh2(k.x, k.y);
    ko.y = packh2(k.z, k.w);
    ((uint2*)g_qh)[i] = qo;
    ((uint2*)g_kh)[i] = ko;
}

// =====================================================================
// P1: transpose V -> g_vt [bh][d][kv] fp16. Tile 64(kv) x 64(d).
// =====================================================================
__global__ __launch_bounds__(256)
void vt_kernel(const float* __restrict__ V) {
    __shared__ float sT[64 * 68];
    const int kt = blockIdx.x, bh = blockIdx.y;
    const int tid = threadIdx.x;
    const float4* Vg = (const float4*)(V + ((size_t)bh * LSEQ + (size_t)kt * 64) * DH);

    #pragma unroll
    for (int i = 0; i < 4; i++) {
        int idx = tid + i * 256;           // 0..1023
        int row = idx >> 4, c4 = idx & 15;
        ((float4*)sT)[row * 17 + c4] = Vg[row * 16 + c4];
    }
    __syncthreads();

    #pragma unroll
    for (int i = 0; i < 2; i++) {
        int idx = tid + i * 256;           // 0..511
        int d = idx >> 3, ch = idx & 7;    // d 0..63, 8-half chunk
        uint4 o;
        unsigned* ow = (unsigned*)&o;
        #pragma unroll
        for (int j = 0; j < 4; j++) {
            float a = sT[(ch * 8 + 2 * j) * 68 + d];
            float b = sT[(ch * 8 + 2 * j + 1) * 68 + d];
            ow[j] = packh2(a, b);
        }
        *(uint4*)&g_vt[((size_t)bh * 64 + d) * LSEQ + (size_t)kt * 64 + ch * 8] = o;
    }
}

// =====================================================================
// K1 (qk3): e = exp(Q K^T / 64) -> g_e (fp16, unnormalized) + partials.
// fp16 m16n8k16 mma. CTA 128x128 tile, 256 thr, warp tile 64x32.
// smem: sQh[128][72]h @0 (18432B), sKh[128][72]h @18432,
//       overlay sEh[128][136]h @0 (34816B), sRowW[4][128]f @36864.
// =====================================================================
#define QK_SMEM_BYTES (36864 + 2048)

__global__ __launch_bounds__(256)
void qk3_kernel(float* __restrict__ dummy) {
    extern __shared__ char sm[];
    __half* sQh = (__half*)sm;
    __half* sKh = (__half*)(sm + 18432);
    __half* sEh = (__half*)sm;                  // overlay after mma
    float*  sRowW = (float*)(sm + 36864);
    const unsigned sbase = (unsigned)__cvta_generic_to_shared(sm);
    const unsigned* uQ = (const unsigned*)sQh;
    const unsigned* uK = (const unsigned*)sKh;
    unsigned* uE = (unsigned*)sEh;

    const int nt = blockIdx.x, mt = blockIdx.y, bh = blockIdx.z;
    const int tid = threadIdx.x;
    const int warp = tid >> 5, lane = tid & 31;
    const int g = lane >> 2, tg = lane & 3;
    const int wm = warp >> 2;   // 0..1
    const int wn = warp & 3;    // 0..3

    // stage Q,K fp16 tiles via cp.async (128 rows x 64 halfs each)
    {
        const __half* Qg = g_qh + ((size_t)bh * LSEQ + (size_t)mt * 128) * DH;
        const __half* Kg = g_kh + ((size_t)bh * LSEQ + (size_t)nt * 128) * DH;
        #pragma unroll
        for (int i = 0; i < 4; i++) {
            int idx = tid + i * 256;          // 0..1023
            int row = idx >> 3, ch = idx & 7;
            cpa16(sbase + row * 144 + ch * 16, Qg + row * 64 + ch * 8);
            cpa16(sbase + 18432 + row * 144 + ch * 16, Kg + row * 64 + ch * 8);
        }
        asm volatile("cp.async.commit_group;");
        asm volatile("cp.async.wait_group 0;");
    }
    __syncthreads();

    float acc[4][4][4];
    #pragma unroll
    for (int mi = 0; mi < 4; mi++)
        #pragma unroll
        for (int ni = 0; ni < 4; ni++)
            #pragma unroll
            for (int j = 0; j < 4; j++) acc[mi][ni][j] = 0.f;

    #pragma unroll
    for (int ks = 0; ks < 4; ks++) {        // k16 steps over D=64
        unsigned a[4][4], b[4][2];
        #pragma unroll
        for (int mi = 0; mi < 4; mi++) {
            int row = wm * 64 + mi * 16;
            a[mi][0] = uQ[(row + g) * 36 + ks * 8 + tg];
            a[mi][1] = uQ[(row + 8 + g) * 36 + ks * 8 + tg];
            a[mi][2] = uQ[(row + g) * 36 + ks * 8 + tg + 4];
            a[mi][3] = uQ[(row + 8 + g) * 36 + ks * 8 + tg + 4];
        }
        #pragma unroll
        for (int ni = 0; ni < 4; ni++) {
            int col = wn * 32 + ni * 8;
            b[ni][0] = uK[(col + g) * 36 + ks * 8 + tg];
            b[ni][1] = uK[(col + g) * 36 + ks * 8 + tg + 4];
        }
        #pragma unroll
        for (int mi = 0; mi < 4; mi++)
            #pragma unroll
            for (int ni = 0; ni < 4; ni++)
                mma16(acc[mi][ni], a[mi], b[ni][0], b[ni][1]);
    }
    __syncthreads();   // staging dead; sEh overlay begins

    // epilogue: exp, partial row sums, pack fp16 into sEh
    float rs0[4] = {0.f, 0.f, 0.f, 0.f};
    float rs1[4] = {0.f, 0.f, 0.f, 0.f};
    #pragma unroll
    for (int mi = 0; mi < 4; mi++) {
        int row = wm * 64 + mi * 16 + g;
        #pragma unroll
        for (int ni = 0; ni < 4; ni++) {
            int cw = wn * 16 + ni * 4 + tg;     // u32 col index (col/2)
            float e0 = fexp(acc[mi][ni][0]);
            float e1 = fexp(acc[mi][ni][1]);
            float e2 = fexp(acc[mi][ni][2]);
            float e3 = fexp(acc[mi][ni][3]);
            rs0[mi] += e0 + e1;
            rs1[mi] += e2 + e3;
            uE[row * 68 + cw]       = packh2(e0, e1);
            uE[(row + 8) * 68 + cw] = packh2(e2, e3);
        }
    }
    #pragma unroll
    for (int o = 1; o <= 2; o <<= 1) {
        #pragma unroll
        for (int mi = 0; mi < 4; mi++) {
            rs0[mi] += __shfl_xor_sync(0xffffffffu, rs0[mi], o);
            rs1[mi] += __shfl_xor_sync(0xffffffffu, rs1[mi], o);
        }
    }
    if (tg == 0) {
        #pragma unroll
        for (int mi = 0; mi < 4; mi++) {
            sRowW[wn * 128 + wm * 64 + mi * 16 + g]     = rs0[mi];
            sRowW[wn * 128 + wm * 64 + mi * 16 + 8 + g] = rs1[mi];
        }
    }
    __syncthreads();

    // coalesced fp16 store: 128 rows x 256 B
    {
        __half* eg = g_e + ((size_t)bh * LSEQ + (size_t)mt * 128) * LSEQ
                         + (size_t)nt * 128;
        #pragma unroll
        for (int i = 0; i < 8; i++) {
            int idx = tid + i * 256;          // 0..2047
            int row = idx >> 4, ch = idx & 15;
            uint4 o;
            o.x = uE[row * 68 + ch * 4 + 0];
            o.y = uE[row * 68 + ch * 4 + 1];
            o.z = uE[row * 68 + ch * 4 + 2];
            o.w = uE[row * 68 + ch * 4 + 3];
            *(uint4*)&eg[(size_t)row * LSEQ + ch * 8] = o;
        }
    }
    if (tid < 128) {
        float s = (sRowW[tid] + sRowW[128 + tid]) +
                  (sRowW[256 + tid] + sRowW[384 + tid]);
        g_partial[((size_t)bh * 2048 + (size_t)mt * 128 + tid) * 16 + nt] = s;
    }
}

// =====================================================================
// K2 (av4): read fp16 e + fp16 Vt (cp.async double-buffer);
// write normalized fp32 att; res = (sum e*v) * inv via fp16 mma.
// CTA 64 rows x 64 dh, 256 thr, warp tile 16x32.
// smem: sE[2][64*72]h (9216B ea) @0, sVt[2][64*72]h @18432, sInv[64]f @36864
// =====================================================================
#define AV_SMEM_BYTES (36864 + 256)

__global__ __launch_bounds__(256)
void av4_kernel(float* __restrict__ att, float* __restrict__ res) {
    extern __shared__ char sm[];
    float* sInv = (float*)(sm + 36864);
    const unsigned sbase = (unsigned)__cvta_generic_to_shared(sm);

    const int mt = blockIdx.x, bh = blockIdx.y;
    const int tid = threadIdx.x;
    const int warp = tid >> 5, lane = tid & 31;
    const int g = lane >> 2, tg = lane & 3;
    const int wm = warp >> 1;   // 0..3
    const int wn = warp & 1;    // 0..1

    if (tid < 64) {
        const float* p = &g_partial[((size_t)bh * 2048 + (size_t)mt * 64 + tid) * 16];
        float s = 0.f;
        #pragma unroll
        for (int j = 0; j < 16; j++) s += p[j];
        sInv[tid] = 1.0f / s;
    }

    const __half* Eg = g_e + ((size_t)bh * LSEQ + (size_t)mt * 64) * LSEQ;
    const __half* Vt = g_vt + (size_t)bh * 64 * LSEQ;

    const unsigned eOff[2] = { 0u, 9216u };
    const unsigned vOff[2] = { 18432u, 18432u + 9216u };
    const int srow = tid >> 3;          // 0..31 (+32 on second chunk batch)
    const int sch  = tid & 7;

    // prologue: prefetch kt=0
    #pragma unroll
    for (int h = 0; h < 2; h++) {
        int row = srow + h * 32;
        cpa16(sbase + eOff[0] + row * 144 + sch * 16,
              Eg + (size_t)row * LSEQ + sch * 8);
        cpa16(sbase + vOff[0] + row * 144 + sch * 16,
              Vt + (size_t)row * LSEQ + sch * 8);
    }
    asm volatile("cp.async.commit_group;");

    float acc[4][4];
    #pragma unroll
    for (int ni = 0; ni < 4; ni++)
        #pragma unroll
        for (int j = 0; j < 4; j++) acc[ni][j] = 0.f;

    __syncthreads();   // sInv ready
    float4* attW = (float4*)(att + ((size_t)bh * LSEQ + (size_t)mt * 64) * LSEQ);

    for (int kt = 0; kt < 32; kt++) {
        const int cur = kt & 1, nxt = cur ^ 1;
        if (kt + 1 < 32) {
            #pragma unroll
            for (int h = 0; h < 2; h++) {
                int row = srow + h * 32;
                cpa16(sbase + eOff[nxt] + row * 144 + sch * 16,
                      Eg + (size_t)row * LSEQ + (kt + 1) * 64 + sch * 8);
                cpa16(sbase + vOff[nxt] + row * 144 + sch * 16,
                      Vt + (size_t)row * LSEQ + (kt + 1) * 64 + sch * 8);
            }
            asm volatile("cp.async.commit_group;");
            asm volatile("cp.async.wait_group 1;");
        } else {
            asm volatile("cp.async.wait_group 0;");
        }
        __syncthreads();

        const unsigned* uE = (const unsigned*)(sm + eOff[cur]);
        const unsigned* uV = (const unsigned*)(sm + vOff[cur]);

        // normalized fp32 att write (coalesced)
        #pragma unroll
        for (int i = 0; i < 4; i++) {
            int idx = tid + i * 256;          // 0..1023
            int row = idx >> 4, c4 = idx & 15;
            float inv = sInv[row];
            unsigned w0 = uE[row * 36 + c4 * 2];
            unsigned w1 = uE[row * 36 + c4 * 2 + 1];
            float2 lo = __half22float2(*(__half2*)&w0);
            float2 hi = __half22float2(*(__half2*)&w1);
            float4 v = make_float4(lo.x * inv, lo.y * inv, hi.x * inv, hi.y * inv);
            attW[(size_t)row * 512 + kt * 16 + c4] = v;
        }

        // fp16 mma: acc += E * Vt^T
        #pragma unroll
        for (int ks = 0; ks < 4; ks++) {
            unsigned a[4], b[4][2];
            int row0 = wm * 16;
            a[0] = uE[(row0 + g) * 36 + ks * 8 + tg];
            a[1] = uE[(row0 + 8 + g) * 36 + ks * 8 + tg];
            a[2] = uE[(row0 + g) * 36 + ks * 8 + tg + 4];
            a[3] = uE[(row0 + 8 + g) * 36 + ks * 8 + tg + 4];
            #pragma unroll
            for (int ni = 0; ni < 4; ni++) {
                int col = wn * 32 + ni * 8;
                b[ni][0] = uV[(col + g) * 36 + ks * 8 + tg];
                b[ni][1] = uV[(col + g) * 36 + ks * 8 + tg + 4];
            }
            #pragma unroll
            for (int ni = 0; ni < 4; ni++)
                mma16(acc[ni], a, b[ni][0], b[ni][1]);
        }
        __syncthreads();
    }

    const float invA = sInv[wm * 16 + g];
    const float invB = sInv[wm * 16 + 8 + g];
    float* resR = res + ((size_t)bh * LSEQ + (size_t)mt * 64) * DH;
    #pragma unroll
    for (int ni = 0; ni < 4; ni++) {
        int row = wm * 16 + g;
        int col = wn * 32 + ni * 8 + 2 * tg;
        *(float2*)&resR[(size_t)row * DH + col] =
            make_float2(acc[ni][0] * invA, acc[ni][1] * invA);
        *(float2*)&resR[(size_t)(row + 8) * DH + col] =
            make_float2(acc[ni][2] * invB, acc[ni][3] * invB);
    }
}

// =====================================================================
extern "C" void kernel_launch(void* const* d_in, const int* in_sizes, int n_in,
                              void* d_out, int out_size) {
    const float* Q = (const float*)d_in[0];
    const float* K = (const float*)d_in[1];
    const float* V = (const float*)d_in[2];

    float* out = (float*)d_out;
    float* res = out;
    float* att = out + (size_t)8 * 8 * 2048 * 64;

    cudaFuncSetAttribute(qk3_kernel,
        cudaFuncAttributeMaxDynamicSharedMemorySize, QK_SMEM_BYTES);
    cudaFuncSetAttribute(av4_kernel,
        cudaFuncAttributeMaxDynamicSharedMemorySize, AV_SMEM_BYTES);

    prep_qk_kernel<<<(8 * 8 * 2048 * 64 / 4) / 256, 256>>>(Q, K);
    vt_kernel<<<dim3(32, 64), 256>>>(V);

    dim3 gA(16, 16, 64);
    qk3_kernel<<<gA, 256, QK_SMEM_BYTES>>>(nullptr);

    dim3 gC(32, 64);
    av4_kernel<<<gC, 256, AV_SMEM_BYTES>>>(att, res);
}

// round 15
// speedup vs baseline: 1.7918x; 1.1029x over previous
#include <cuda_runtime.h>
#include <cuda_fp16.h>

// B=8, H=8, L=2048, D=64, BH=64
#define LSEQ 2048
#define DH   64

__device__ __align__(16) __half g_qh[(size_t)64 * 2048 * 64];    // Q/64 fp16
__device__ __align__(16) __half g_kh[(size_t)64 * 2048 * 64];    // K fp16
__device__ __align__(16) __half g_vt[(size_t)64 * 64 * 2048];    // V^T fp16 [bh][d][kv]

// ---------- helpers ----------
__device__ __forceinline__ void mma16(float* c, const unsigned* a,
                                      unsigned b0, unsigned b1) {
    asm volatile(
        "mma.sync.aligned.m16n8k16.row.col.f32.f16.f16.f32 "
        "{%0,%1,%2,%3}, {%4,%5,%6,%7}, {%8,%9}, {%0,%1,%2,%3};"
        : "+f"(c[0]), "+f"(c[1]), "+f"(c[2]), "+f"(c[3])
        : "r"(a[0]), "r"(a[1]), "r"(a[2]), "r"(a[3]), "r"(b0), "r"(b1));
}

__device__ __forceinline__ void cpa16(unsigned s, const void* g) {
    asm volatile("cp.async.cg.shared.global [%0], [%1], 16;" :: "r"(s), "l"(g));
}

__device__ __forceinline__ float fexp(float x) {
    x = fmaxf(fminf(x, 80.0f), -80.0f);
    const float L2E = 1.4426950408889634f;
    float t = fmaf(x, L2E, 12582912.0f);
    float n = t - 12582912.0f;
    float f = fmaf(x, L2E, -n);
    float p = 1.33335581e-3f;
    p = fmaf(p, f, 9.61812910e-3f);
    p = fmaf(p, f, 5.55041086e-2f);
    p = fmaf(p, f, 2.40226507e-1f);
    p = fmaf(p, f, 6.93147181e-1f);
    p = fmaf(p, f, 1.0f);
    unsigned bits = (unsigned)(((int)n + 127) << 23);
    return p * __uint_as_float(bits);
}

__device__ __forceinline__ unsigned packh2(float a, float b) {
    __half2 h = __floats2half2_rn(a, b);
    return *(unsigned*)&h;
}

// =====================================================================
// P0: Q*(1/64), K -> fp16
// =====================================================================
__global__ __launch_bounds__(256)
void prep_qk_kernel(const float* __restrict__ Q, const float* __restrict__ K) {
    size_t i = (size_t)blockIdx.x * 256 + threadIdx.x;
    const float4 q = ((const float4*)Q)[i];
    const float4 k = ((const float4*)K)[i];
    const float s = 1.0f / 64.0f;
    uint2 qo, ko;
    qo.x = packh2(q.x * s, q.y * s);
    qo.y = packh2(q.z * s, q.w * s);
    ko.x = packh2(k.x, k.y);
    ko.y = packh2(k.z, k.w);
    ((uint2*)g_qh)[i] = qo;
    ((uint2*)g_kh)[i] = ko;
}

// =====================================================================
// P1: V -> V^T fp16 [bh][d][kv]
// =====================================================================
__global__ __launch_bounds__(256)
void vt_kernel(const float* __restrict__ V) {
    __shared__ float sT[64 * 68];
    const int kt = blockIdx.x, bh = blockIdx.y;
    const int tid = threadIdx.x;
    const float4* Vg = (const float4*)(V + ((size_t)bh * LSEQ + (size_t)kt * 64) * DH);

    #pragma unroll
    for (int i = 0; i < 4; i++) {
        int idx = tid + i * 256;
        int row = idx >> 4, c4 = idx & 15;
        ((float4*)sT)[row * 17 + c4] = Vg[row * 16 + c4];
    }
    __syncthreads();

    #pragma unroll
    for (int i = 0; i < 2; i++) {
        int idx = tid + i * 256;
        int d = idx >> 3, ch = idx & 7;
        uint4 o;
        unsigned* ow = (unsigned*)&o;
        #pragma unroll
        for (int j = 0; j < 4; j++) {
            float a = sT[(ch * 8 + 2 * j) * 68 + d];
            float b = sT[(ch * 8 + 2 * j + 1) * 68 + d];
            ow[j] = packh2(a, b);
        }
        *(uint4*)&g_vt[((size_t)bh * 64 + d) * LSEQ + (size_t)kt * 64 + ch * 8] = o;
    }
}

// =====================================================================
// Fused attention: one CTA = 128 q-rows x all 2048 cols.
// Pass A: S=QK^T, exp, row sums (registers). Pass B: recompute S,
// write normalized fp32 att, accumulate O = P@V, write res.
// 8 warps, warp = 16 rows. smem layout (bytes):
//   sK[2]:  @0, @18432       (128 rows x 36 u32, stride 144B)
//   sVt[2]: @36864, @54272   (64 rows x 68 u32, stride 272B)
//   sP:     @71680           (128 x 68 u32)
//   sInv:   @106496          (128 f32)
// =====================================================================
#define KOFF0 0u
#define KOFF1 18432u
#define VOFF0 36864u
#define VOFF1 54272u
#define POFF  71680u
#define IOFF  106496u
#define AT_SMEM (106496 + 512)

__global__ __launch_bounds__(256, 2)
void attn_kernel(float* __restrict__ att, float* __restrict__ res) {
    extern __shared__ char sm[];
    float* sInv = (float*)(sm + IOFF);
    unsigned* sPu = (unsigned*)(sm + POFF);
    const unsigned sbase = (unsigned)__cvta_generic_to_shared(sm);

    const int mt = blockIdx.x, bh = blockIdx.y;
    const int tid = threadIdx.x;
    const int w = tid >> 5, lane = tid & 31;
    const int g = lane >> 2, tg = lane & 3;
    const int w16 = w * 16;

    const __half* Kg  = g_kh + (size_t)bh * LSEQ * DH;
    const __half* Vtg = g_vt + (size_t)bh * 64 * LSEQ;

    // ---- Q fragments (registers, once) ----
    unsigned aq[4][4];
    {
        const unsigned* Qu = (const unsigned*)(g_qh + ((size_t)bh * LSEQ + mt * 128) * DH);
        #pragma unroll
        for (int ks = 0; ks < 4; ks++) {
            aq[ks][0] = Qu[(w16 + g) * 32 + ks * 8 + tg];
            aq[ks][1] = Qu[(w16 + 8 + g) * 32 + ks * 8 + tg];
            aq[ks][2] = Qu[(w16 + g) * 32 + ks * 8 + tg + 4];
            aq[ks][3] = Qu[(w16 + 8 + g) * 32 + ks * 8 + tg + 4];
        }
    }

    // ================= PASS A: row sums =================
    {
        #pragma unroll
        for (int i = 0; i < 4; i++) {
            int idx = tid + i * 256;
            int row = idx >> 3, ch = idx & 7;
            cpa16(sbase + KOFF0 + row * 144 + ch * 16, Kg + (size_t)row * 64 + ch * 8);
        }
        asm volatile("cp.async.commit_group;");
    }
    float s0 = 0.f, s1 = 0.f;
    for (int nt = 0; nt < 16; nt++) {
        const int cur = nt & 1;
        if (nt < 15) {
            unsigned dst = cur ? KOFF0 : KOFF1;
            #pragma unroll
            for (int i = 0; i < 4; i++) {
                int idx = tid + i * 256;
                int row = idx >> 3, ch = idx & 7;
                cpa16(sbase + dst + row * 144 + ch * 16,
                      Kg + ((size_t)(nt + 1) * 128 + row) * 64 + ch * 8);
            }
            asm volatile("cp.async.commit_group;");
            asm volatile("cp.async.wait_group 1;");
        } else {
            asm volatile("cp.async.wait_group 0;");
        }
        __syncthreads();
        const unsigned* uK = (const unsigned*)(sm + (cur ? KOFF1 : KOFF0));

        #pragma unroll
        for (int kc = 0; kc < 8; kc++) {
            float aS[2][4] = {{0.f,0.f,0.f,0.f},{0.f,0.f,0.f,0.f}};
            #pragma unroll
            for (int ks = 0; ks < 4; ks++) {
                unsigned b00 = uK[(16 * kc + g) * 36 + ks * 8 + tg];
                unsigned b01 = uK[(16 * kc + g) * 36 + ks * 8 + tg + 4];
                unsigned b10 = uK[(16 * kc + 8 + g) * 36 + ks * 8 + tg];
                unsigned b11 = uK[(16 * kc + 8 + g) * 36 + ks * 8 + tg + 4];
                mma16(aS[0], aq[ks], b00, b01);
                mma16(aS[1], aq[ks], b10, b11);
            }
            s0 += fexp(aS[0][0]) + fexp(aS[0][1]) + fexp(aS[1][0]) + fexp(aS[1][1]);
            s1 += fexp(aS[0][2]) + fexp(aS[0][3]) + fexp(aS[1][2]) + fexp(aS[1][3]);
        }
        __syncthreads();
    }
    // reduce over tg lanes (same g)
    #pragma unroll
    for (int o = 1; o <= 2; o <<= 1) {
        s0 += __shfl_xor_sync(0xffffffffu, s0, o);
        s1 += __shfl_xor_sync(0xffffffffu, s1, o);
    }
    if (tg == 0) {
        sInv[w16 + g]     = 1.0f / s0;
        sInv[w16 + 8 + g] = 1.0f / s1;
    }
    __syncthreads();
    const float invA = sInv[w16 + g];
    const float invB = sInv[w16 + 8 + g];

    // ================= PASS B: att + O =================
    {
        #pragma unroll
        for (int i = 0; i < 4; i++) {
            int idx = tid + i * 256;
            int row = idx >> 3, ch = idx & 7;
            cpa16(sbase + KOFF0 + row * 144 + ch * 16, Kg + (size_t)row * 64 + ch * 8);
        }
        #pragma unroll
        for (int i = 0; i < 4; i++) {
            int idx = tid + i * 256;
            int d = idx >> 4, ch = idx & 15;
            cpa16(sbase + VOFF0 + d * 272 + ch * 16, Vtg + (size_t)d * LSEQ + ch * 8);
        }
        asm volatile("cp.async.commit_group;");
    }

    float accO[8][4];
    #pragma unroll
    for (int nd = 0; nd < 8; nd++)
        #pragma unroll
        for (int j = 0; j < 4; j++) accO[nd][j] = 0.f;

    float* attBase = att + ((size_t)bh * LSEQ + mt * 128) * LSEQ;

    for (int nt = 0; nt < 16; nt++) {
        const int cur = nt & 1;
        if (nt < 15) {
            unsigned kdst = cur ? KOFF0 : KOFF1;
            unsigned vdst = cur ? VOFF0 : VOFF1;
            #pragma unroll
            for (int i = 0; i < 4; i++) {
                int idx = tid + i * 256;
                int row = idx >> 3, ch = idx & 7;
                cpa16(sbase + kdst + row * 144 + ch * 16,
                      Kg + ((size_t)(nt + 1) * 128 + row) * 64 + ch * 8);
            }
            #pragma unroll
            for (int i = 0; i < 4; i++) {
                int idx = tid + i * 256;
                int d = idx >> 4, ch = idx & 15;
                cpa16(sbase + vdst + d * 272 + ch * 16,
                      Vtg + (size_t)d * LSEQ + (nt + 1) * 128 + ch * 8);
            }
            asm volatile("cp.async.commit_group;");
            asm volatile("cp.async.wait_group 1;");
        } else {
            asm volatile("cp.async.wait_group 0;");
        }
        __syncthreads();
        const unsigned* uK  = (const unsigned*)(sm + (cur ? KOFF1 : KOFF0));
        const unsigned* uVt = (const unsigned*)(sm + (cur ? VOFF1 : VOFF0));

        #pragma unroll
        for (int kc = 0; kc < 8; kc++) {
            float aS[2][4] = {{0.f,0.f,0.f,0.f},{0.f,0.f,0.f,0.f}};
            #pragma unroll
            for (int ks = 0; ks < 4; ks++) {
                unsigned b00 = uK[(16 * kc + g) * 36 + ks * 8 + tg];
                unsigned b01 = uK[(16 * kc + g) * 36 + ks * 8 + tg + 4];
                unsigned b10 = uK[(16 * kc + 8 + g) * 36 + ks * 8 + tg];
                unsigned b11 = uK[(16 * kc + 8 + g) * 36 + ks * 8 + tg + 4];
                mma16(aS[0], aq[ks], b00, b01);
                mma16(aS[1], aq[ks], b10, b11);
            }
            // exp + pack to fp16 P fragments (A-layout for AV mma)
            unsigned pA[4];
            pA[0] = packh2(fexp(aS[0][0]), fexp(aS[0][1]));
            pA[1] = packh2(fexp(aS[0][2]), fexp(aS[0][3]));
            pA[2] = packh2(fexp(aS[1][0]), fexp(aS[1][1]));
            pA[3] = packh2(fexp(aS[1][2]), fexp(aS[1][3]));
            // stage P for coalesced att store
            sPu[(w16 + g) * 68 + 8 * kc + tg]          = pA[0];
            sPu[(w16 + 8 + g) * 68 + 8 * kc + tg]      = pA[1];
            sPu[(w16 + g) * 68 + 8 * kc + 4 + tg]      = pA[2];
            sPu[(w16 + 8 + g) * 68 + 8 * kc + 4 + tg]  = pA[3];
            // O += P_chunk @ V_chunk
            #pragma unroll
            for (int nd = 0; nd < 8; nd++) {
                unsigned bv0 = uVt[(nd * 8 + g) * 68 + kc * 8 + tg];
                unsigned bv1 = uVt[(nd * 8 + g) * 68 + kc * 8 + tg + 4];
                mma16(accO[nd], pA, bv0, bv1);
            }
        }
        __syncthreads();

        // coalesced normalized att store (128 rows x 128 cols fp32)
        #pragma unroll
        for (int i = 0; i < 16; i++) {
            int idx = tid + i * 256;          // 0..4095
            int row = idx >> 5, cu2 = idx & 31;
            unsigned w0 = sPu[row * 68 + cu2 * 2];
            unsigned w1 = sPu[row * 68 + cu2 * 2 + 1];
            float inv = sInv[row];
            float2 lo = __half22float2(*(__half2*)&w0);
            float2 hi = __half22float2(*(__half2*)&w1);
            float4 v = make_float4(lo.x * inv, lo.y * inv, hi.x * inv, hi.y * inv);
            *(float4*)&attBase[(size_t)row * LSEQ + nt * 128 + cu2 * 4] = v;
        }
    }

    // ---- res ----
    float* resR = res + ((size_t)bh * LSEQ + mt * 128) * DH;
    #pragma unroll
    for (int nd = 0; nd < 8; nd++) {
        int row = w16 + g;
        int col = nd * 8 + 2 * tg;
        *(float2*)&resR[(size_t)row * DH + col] =
            make_float2(accO[nd][0] * invA, accO[nd][1] * invA);
        *(float2*)&resR[(size_t)(row + 8) * DH + col] =
            make_float2(accO[nd][2] * invB, accO[nd][3] * invB);
    }
}

// =====================================================================
extern "C" void kernel_launch(void* const* d_in, const int* in_sizes, int n_in,
                              void* d_out, int out_size) {
    const float* Q = (const float*)d_in[0];
    const float* K = (const float*)d_in[1];
    const float* V = (const float*)d_in[2];

    float* out = (float*)d_out;
    float* res = out;
    float* att = out + (size_t)8 * 8 * 2048 * 64;

    cudaFuncSetAttribute(attn_kernel,
        cudaFuncAttributeMaxDynamicSharedMemorySize, AT_SMEM);

    prep_qk_kernel<<<(8 * 8 * 2048 * 64 / 4) / 256, 256>>>(Q, K);
    vt_kernel<<<dim3(32, 64), 256>>>(V);

    dim3 g(16, 64);
    attn_kernel<<<g, 256, AT_SMEM>>>(att, res);
}

// round 17
// speedup vs baseline: 2.0231x; 1.1291x over previous
#include <cuda_runtime.h>
#include <cuda_fp16.h>

// B=8, H=8, L=2048, D=64, BH=64
#define LSEQ 2048
#define DH   64

__device__ __align__(16) __half g_e[(size_t)64 * 2048 * 2048];   // unnormalized exp, fp16
__device__ __align__(16) __half g_qh[(size_t)64 * 2048 * 64];    // Q/64 fp16
__device__ __align__(16) __half g_kh[(size_t)64 * 2048 * 64];    // K fp16
__device__ __align__(16) __half g_vt[(size_t)64 * 64 * 2048];    // V^T fp16 [bh][d][kv]

// ---------- helpers ----------
__device__ __forceinline__ void mma16(float* c, const unsigned* a,
                                      unsigned b0, unsigned b1) {
    asm volatile(
        "mma.sync.aligned.m16n8k16.row.col.f32.f16.f16.f32 "
        "{%0,%1,%2,%3}, {%4,%5,%6,%7}, {%8,%9}, {%0,%1,%2,%3};"
        : "+f"(c[0]), "+f"(c[1]), "+f"(c[2]), "+f"(c[3])
        : "r"(a[0]), "r"(a[1]), "r"(a[2]), "r"(a[3]), "r"(b0), "r"(b1));
}

__device__ __forceinline__ void cpa16(unsigned s, const void* g) {
    asm volatile("cp.async.cg.shared.global [%0], [%1], 16;" :: "r"(s), "l"(g));
}

__device__ __forceinline__ float fexp(float x) {
    x = fmaxf(fminf(x, 80.0f), -80.0f);
    const float L2E = 1.4426950408889634f;
    float t = fmaf(x, L2E, 12582912.0f);
    float n = t - 12582912.0f;
    float f = fmaf(x, L2E, -n);
    float p = 1.33335581e-3f;
    p = fmaf(p, f, 9.61812910e-3f);
    p = fmaf(p, f, 5.55041086e-2f);
    p = fmaf(p, f, 2.40226507e-1f);
    p = fmaf(p, f, 6.93147181e-1f);
    p = fmaf(p, f, 1.0f);
    unsigned bits = (unsigned)(((int)n + 127) << 23);
    return p * __uint_as_float(bits);
}

__device__ __forceinline__ unsigned packh2(float a, float b) {
    __half2 h = __floats2half2_rn(a, b);
    return *(unsigned*)&h;
}

// =====================================================================
// P0: Q*(1/64), K -> fp16
// =====================================================================
__global__ __launch_bounds__(256)
void prep_qk_kernel(const float* __restrict__ Q, const float* __restrict__ K) {
    size_t i = (size_t)blockIdx.x * 256 + threadIdx.x;
    const float4 q = ((const float4*)Q)[i];
    const float4 k = ((const float4*)K)[i];
    const float s = 1.0f / 64.0f;
    uint2 qo, ko;
    qo.x = packh2(q.x * s, q.y * s);
    qo.y = packh2(q.z * s, q.w * s);
    ko.x = packh2(k.x, k.y);
    ko.y = packh2(k.z, k.w);
    ((uint2*)g_qh)[i] = qo;
    ((uint2*)g_kh)[i] = ko;
}

// =====================================================================
// P1: V -> V^T fp16 [bh][d][kv]
// =====================================================================
__global__ __launch_bounds__(256)
void vt_kernel(const float* __restrict__ V) {
    __shared__ float sT[64 * 68];
    const int kt = blockIdx.x, bh = blockIdx.y;
    const int tid = threadIdx.x;
    const float4* Vg = (const float4*)(V + ((size_t)bh * LSEQ + (size_t)kt * 64) * DH);

    #pragma unroll
    for (int i = 0; i < 4; i++) {
        int idx = tid + i * 256;
        int row = idx >> 4, c4 = idx & 15;
        ((float4*)sT)[row * 17 + c4] = Vg[row * 16 + c4];
    }
    __syncthreads();

    #pragma unroll
    for (int i = 0; i < 2; i++) {
        int idx = tid + i * 256;
        int d = idx >> 3, ch = idx & 7;
        uint4 o;
        unsigned* ow = (unsigned*)&o;
        #pragma unroll
        for (int j = 0; j < 4; j++) {
            float a = sT[(ch * 8 + 2 * j) * 68 + d];
            float b = sT[(ch * 8 + 2 * j + 1) * 68 + d];
            ow[j] = packh2(a, b);
        }
        *(uint4*)&g_vt[((size_t)bh * 64 + d) * LSEQ + (size_t)kt * 64 + ch * 8] = o;
    }
}

// =====================================================================
// Fused attention, e-scratch variant. CTA = 128 q-rows x all cols.
// Pass A: S=QK^T, exp, row sums; e tile -> g_e (fp16, mostly L2-resident).
// Pass B: load e + Vt, write normalized fp32 att, O = P@V, write res.
// smem (bytes):
//  Pass A: sK[2] @0/@18432 (128 x 144B), sP @36864 (128 x 272B)
//  Pass B: sE[2] @0/@34816 (128 x 272B), sV[2] @69632/@87040 (64 x 272B)
//  sInv @104448 (512B)
// =====================================================================
#define KOFF0 0u
#define KOFF1 18432u
#define PAOFF 36864u
#define EOFF0 0u
#define EOFF1 34816u
#define VOFF0 69632u
#define VOFF1 87040u
#define IOFF  104448u
#define AT_SMEM (104448 + 512)

__global__ __launch_bounds__(256, 2)
void attn2_kernel(float* __restrict__ att, float* __restrict__ res) {
    extern __shared__ char sm[];
    float* sInv = (float*)(sm + IOFF);
    unsigned* sPu = (unsigned*)(sm + PAOFF);
    const unsigned sbase = (unsigned)__cvta_generic_to_shared(sm);

    const int mt = blockIdx.x, bh = blockIdx.y;
    const int tid = threadIdx.x;
    const int w = tid >> 5, lane = tid & 31;
    const int g = lane >> 2, tg = lane & 3;
    const int w16 = w * 16;

    const __half* Kg  = g_kh + (size_t)bh * LSEQ * DH;
    const __half* Vtg = g_vt + (size_t)bh * 64 * LSEQ;
    __half* Eg = g_e + ((size_t)bh * LSEQ + mt * 128) * LSEQ;

    // ---- Q fragments ----
    unsigned aq[4][4];
    {
        const unsigned* Qu = (const unsigned*)(g_qh + ((size_t)bh * LSEQ + mt * 128) * DH);
        #pragma unroll
        for (int ks = 0; ks < 4; ks++) {
            aq[ks][0] = Qu[(w16 + g) * 32 + ks * 8 + tg];
            aq[ks][1] = Qu[(w16 + 8 + g) * 32 + ks * 8 + tg];
            aq[ks][2] = Qu[(w16 + g) * 32 + ks * 8 + tg + 4];
            aq[ks][3] = Qu[(w16 + 8 + g) * 32 + ks * 8 + tg + 4];
        }
    }

    // ================= PASS A: e = exp(QK^T) -> g_e, row sums =================
    {
        #pragma unroll
        for (int i = 0; i < 4; i++) {
            int idx = tid + i * 256;
            int row = idx >> 3, ch = idx & 7;
            cpa16(sbase + KOFF0 + row * 144 + ch * 16, Kg + (size_t)row * 64 + ch * 8);
        }
        asm volatile("cp.async.commit_group;");
    }
    float s0 = 0.f, s1 = 0.f;
    for (int nt = 0; nt < 16; nt++) {
        const int cur = nt & 1;
        if (nt < 15) {
            unsigned dst = cur ? KOFF0 : KOFF1;
            #pragma unroll
            for (int i = 0; i < 4; i++) {
                int idx = tid + i * 256;
                int row = idx >> 3, ch = idx & 7;
                cpa16(sbase + dst + row * 144 + ch * 16,
                      Kg + ((size_t)(nt + 1) * 128 + row) * 64 + ch * 8);
            }
            asm volatile("cp.async.commit_group;");
            asm volatile("cp.async.wait_group 1;");
        } else {
            asm volatile("cp.async.wait_group 0;");
        }
        __syncthreads();
        const unsigned* uK = (const unsigned*)(sm + (cur ? KOFF1 : KOFF0));

        #pragma unroll
        for (int kc = 0; kc < 8; kc++) {
            float aS[2][4] = {{0.f,0.f,0.f,0.f},{0.f,0.f,0.f,0.f}};
            #pragma unroll
            for (int ks = 0; ks < 4; ks++) {
                unsigned b00 = uK[(16 * kc + g) * 36 + ks * 8 + tg];
                unsigned b01 = uK[(16 * kc + g) * 36 + ks * 8 + tg + 4];
                unsigned b10 = uK[(16 * kc + 8 + g) * 36 + ks * 8 + tg];
                unsigned b11 = uK[(16 * kc + 8 + g) * 36 + ks * 8 + tg + 4];
                mma16(aS[0], aq[ks], b00, b01);
                mma16(aS[1], aq[ks], b10, b11);
            }
            float e00 = fexp(aS[0][0]), e01 = fexp(aS[0][1]);
            float e02 = fexp(aS[0][2]), e03 = fexp(aS[0][3]);
            float e10 = fexp(aS[1][0]), e11 = fexp(aS[1][1]);
            float e12 = fexp(aS[1][2]), e13 = fexp(aS[1][3]);
            s0 += e00 + e01 + e10 + e11;
            s1 += e02 + e03 + e12 + e13;
            sPu[(w16 + g) * 68 + 8 * kc + tg]         = packh2(e00, e01);
            sPu[(w16 + 8 + g) * 68 + 8 * kc + tg]     = packh2(e02, e03);
            sPu[(w16 + g) * 68 + 8 * kc + 4 + tg]     = packh2(e10, e11);
            sPu[(w16 + 8 + g) * 68 + 8 * kc + 4 + tg] = packh2(e12, e13);
        }
        __syncthreads();

        // coalesced fp16 e-tile store (128 rows x 256 B)
        #pragma unroll
        for (int i = 0; i < 8; i++) {
            int idx = tid + i * 256;          // 0..2047
            int row = idx >> 4, ch = idx & 15;
            uint4 o;
            o.x = sPu[row * 68 + ch * 4 + 0];
            o.y = sPu[row * 68 + ch * 4 + 1];
            o.z = sPu[row * 68 + ch * 4 + 2];
            o.w = sPu[row * 68 + ch * 4 + 3];
            *(uint4*)&Eg[(size_t)row * LSEQ + nt * 128 + ch * 8] = o;
        }
    }
    // row-sum reduce over tg lanes
    #pragma unroll
    for (int o = 1; o <= 2; o <<= 1) {
        s0 += __shfl_xor_sync(0xffffffffu, s0, o);
        s1 += __shfl_xor_sync(0xffffffffu, s1, o);
    }
    if (tg == 0) {
        sInv[w16 + g]     = 1.0f / s0;
        sInv[w16 + 8 + g] = 1.0f / s1;
    }
    __syncthreads();
    const float invA = sInv[w16 + g];
    const float invB = sInv[w16 + 8 + g];

    // ================= PASS B: att + O =================
    {
        #pragma unroll
        for (int i = 0; i < 8; i++) {         // E tile nt=0
            int idx = tid + i * 256;
            int row = idx >> 4, ch = idx & 15;
            cpa16(sbase + EOFF0 + row * 272 + ch * 16,
                  Eg + (size_t)row * LSEQ + ch * 8);
        }
        #pragma unroll
        for (int i = 0; i < 4; i++) {         // V tile nt=0
            int idx = tid + i * 256;
            int d = idx >> 4, ch = idx & 15;
            cpa16(sbase + VOFF0 + d * 272 + ch * 16, Vtg + (size_t)d * LSEQ + ch * 8);
        }
        asm volatile("cp.async.commit_group;");
    }

    float accO[8][4];
    #pragma unroll
    for (int nd = 0; nd < 8; nd++)
        #pragma unroll
        for (int j = 0; j < 4; j++) accO[nd][j] = 0.f;

    float* attBase = att + ((size_t)bh * LSEQ + mt * 128) * LSEQ;

    for (int nt = 0; nt < 16; nt++) {
        const int cur = nt & 1;
        if (nt < 15) {
            unsigned edst = cur ? EOFF0 : EOFF1;
            unsigned vdst = cur ? VOFF0 : VOFF1;
            #pragma unroll
            for (int i = 0; i < 8; i++) {
                int idx = tid + i * 256;
                int row = idx >> 4, ch = idx & 15;
                cpa16(sbase + edst + row * 272 + ch * 16,
                      Eg + (size_t)row * LSEQ + (nt + 1) * 128 + ch * 8);
            }
            #pragma unroll
            for (int i = 0; i < 4; i++) {
                int idx = tid + i * 256;
                int d = idx >> 4, ch = idx & 15;
                cpa16(sbase + vdst + d * 272 + ch * 16,
                      Vtg + (size_t)d * LSEQ + (nt + 1) * 128 + ch * 8);
            }
            asm volatile("cp.async.commit_group;");
            asm volatile("cp.async.wait_group 1;");
        } else {
            asm volatile("cp.async.wait_group 0;");
        }
        __syncthreads();
        const unsigned* uE = (const unsigned*)(sm + (cur ? EOFF1 : EOFF0));
        const unsigned* uV = (const unsigned*)(sm + (cur ? VOFF1 : VOFF0));

        // normalized fp32 att store first (DRAM writes overlap the mma below)
        #pragma unroll
        for (int i = 0; i < 16; i++) {
            int idx = tid + i * 256;          // 0..4095
            int row = idx >> 5, cu2 = idx & 31;
            uint2 ww = *(const uint2*)&uE[row * 68 + cu2 * 2];
            float inv = sInv[row];
            float2 lo = __half22float2(*(__half2*)&ww.x);
            float2 hi = __half22float2(*(__half2*)&ww.y);
            float4 v = make_float4(lo.x * inv, lo.y * inv, hi.x * inv, hi.y * inv);
            *(float4*)&attBase[(size_t)row * LSEQ + nt * 128 + cu2 * 4] = v;
        }

        // O += P @ V
        #pragma unroll
        for (int kc = 0; kc < 8; kc++) {
            unsigned a[4];
            a[0] = uE[(w16 + g) * 68 + kc * 8 + tg];
            a[1] = uE[(w16 + 8 + g) * 68 + kc * 8 + tg];
            a[2] = uE[(w16 + g) * 68 + kc * 8 + tg + 4];
            a[3] = uE[(w16 + 8 + g) * 68 + kc * 8 + tg + 4];
            #pragma unroll
            for (int nd = 0; nd < 8; nd++) {
                unsigned bv0 = uV[(nd * 8 + g) * 68 + kc * 8 + tg];
                unsigned bv1 = uV[(nd * 8 + g) * 68 + kc * 8 + tg + 4];
                mma16(accO[nd], a, bv0, bv1);
            }
        }
        __syncthreads();
    }

    // ---- res ----
    float* resR = res + ((size_t)bh * LSEQ + mt * 128) * DH;
    #pragma unroll
    for (int nd = 0; nd < 8; nd++) {
        int row = w16 + g;
        int col = nd * 8 + 2 * tg;
        *(float2*)&resR[(size_t)row * DH + col] =
            make_float2(accO[nd][0] * invA, accO[nd][1] * invA);
        *(float2*)&resR[(size_t)(row + 8) * DH + col] =
            make_float2(accO[nd][2] * invB, accO[nd][3] * invB);
    }
}

// =====================================================================
extern "C" void kernel_launch(void* const* d_in, const int* in_sizes, int n_in,
                              void* d_out, int out_size) {
    const float* Q = (const float*)d_in[0];
    const float* K = (const float*)d_in[1];
    const float* V = (const float*)d_in[2];

    float* out = (float*)d_out;
    float* res = out;
    float* att = out + (size_t)8 * 8 * 2048 * 64;

    cudaFuncSetAttribute(attn2_kernel,
        cudaFuncAttributeMaxDynamicSharedMemorySize, AT_SMEM);

    prep_qk_kernel<<<(8 * 8 * 2048 * 64 / 4) / 256, 256>>>(Q, K);
    vt_kernel<<<dim3(32, 64), 256>>>(V);

    dim3 g(16, 64);
    attn2_kernel<<<g, 256, AT_SMEM>>>(att, res);
}